// round 1
// baseline (speedup 1.0000x reference)
#include <cuda_runtime.h>
#include <math.h>
#include <stdint.h>

#define FF 256   // frames (sequence length)
#define NN 400   // batch*joints (attention batch)
#define CC 128   // channels
#define HH 8     // heads
#define EE 16    // head dim
#define MM 128   // max relative pos
#define DD 257   // emb rows = 2*M+1

// ---------------- scratch (device globals; no allocation allowed) ----------------
__device__ float g_tk[NN * CC];
__device__ float g_tv[NN * CC];
__device__ float g_Q[(size_t)NN * HH * FF * EE];
__device__ float g_K[(size_t)NN * HH * FF * EE];
__device__ float g_V[(size_t)NN * HH * FF * EE];
__device__ float g_Y[(size_t)FF * NN * CC];
__device__ float g_H1[(size_t)FF * NN * CC];

// ---------------- kernel 0: tree_k / tree_v projections (tiny) ----------------
__global__ void __launch_bounds__(128) tree_proj_kernel(
    const float* __restrict__ te, const float* __restrict__ Wk,
    const float* __restrict__ Wv) {
  __shared__ float s[CC];
  int n = blockIdx.x, c = threadIdx.x;
  s[c] = te[n * CC + c];
  __syncthreads();
  float ak = 0.f, av = 0.f;
#pragma unroll 4
  for (int j = 0; j < CC; j++) {
    float t = s[j];
    ak += t * Wk[j * CC + c];
    av += t * Wv[j * CC + c];
  }
  g_tk[n * CC + c] = ak;
  g_tv[n * CC + c] = av;
}

// ---------------- kernel 1: QKV projection + tree add + head scatter ----------------
// grid (1600, 3): blockIdx.x = 64-row tile of the (F*N, C) row space,
// blockIdx.y = which 128-col chunk (0=Q,1=K,2=V). block = 256 threads (16x16 logical).
__global__ void __launch_bounds__(256) qkv_kernel(
    const float* __restrict__ x, const float* __restrict__ Wqkv) {
  extern __shared__ float sm[];
  float* sW = sm;               // 128 x 129 (padded)
  float* sX = sm + 128 * 129;   // 64 x 128
  int m = blockIdx.y;
  int row0 = blockIdx.x * 64;
  int t = threadIdx.x;

  const float* Wc = Wqkv + (size_t)m * 128 * CC;
  for (int i = t; i < 128 * CC; i += 256) {
    int r = i >> 7, c = i & 127;
    sW[r * 129 + c] = Wc[i];
  }
  const float4* xsrc = (const float4*)(x + (size_t)row0 * CC);
  for (int i = t; i < 64 * CC / 4; i += 256) ((float4*)sX)[i] = xsrc[i];
  __syncthreads();

  int tx = t & 15, ty = t >> 4;
  float acc[4][8];
#pragma unroll
  for (int a = 0; a < 4; a++)
#pragma unroll
    for (int b = 0; b < 8; b++) acc[a][b] = 0.f;

#pragma unroll 4
  for (int c = 0; c < CC; c++) {
    float xv[4], wv[8];
#pragma unroll
    for (int rr = 0; rr < 4; rr++) xv[rr] = sX[(ty + rr * 16) * CC + c];
#pragma unroll
    for (int oo = 0; oo < 8; oo++) wv[oo] = sW[(tx + oo * 16) * 129 + c];
#pragma unroll
    for (int rr = 0; rr < 4; rr++)
#pragma unroll
      for (int oo = 0; oo < 8; oo++) acc[rr][oo] += xv[rr] * wv[oo];
  }

  float* dst = (m == 0) ? g_Q : (m == 1) ? g_K : g_V;
  const float* tadd = (m == 1) ? g_tk : (m == 2) ? g_tv : nullptr;
#pragma unroll
  for (int rr = 0; rr < 4; rr++) {
    int r = row0 + ty + rr * 16;
    int f = r / NN, n = r - f * NN;
#pragma unroll
    for (int oo = 0; oo < 8; oo++) {
      int o = tx + oo * 16;
      float v = acc[rr][oo];
      if (tadd) v += tadd[n * CC + o];
      int h = o >> 4, e = o & 15;
      dst[(((size_t)(n * HH + h)) * FF + f) * EE + e] = v;
    }
  }
}

// ---------------- kernel 2: attention with relative position bias ----------------
// grid (4 l-tiles, 8 heads, 400 batch). block = 256 threads.
// thread t: l = t&63 (row in tile), sg = t>>6 (64-wide s chunk). Scores in registers.
__global__ void __launch_bounds__(256, 2) attn_kernel(const float* __restrict__ emb) {
  extern __shared__ float sm[];
  float* sK = sm;            // 4096
  float* sV = sK + 4096;     // 4096
  float* sE = sV + 4096;     // 257*17 = 4369 (padded for conflict-free diagonal gather)
  float* sO = sE + 4369;     // 64*17 = 1088
  float* sR = sO + 1088;     // 512 (row max / row sum)

  int lt = blockIdx.x, h = blockIdx.y, n = blockIdx.z;
  int t = threadIdx.x;
  int l = t & 63, sg = t >> 6;
  int l0 = lt * 64, lg = l0 + l;
  size_t boff = ((size_t)n * HH + h) * FF * EE;

  const float4* K4 = (const float4*)(g_K + boff);
  const float4* V4 = (const float4*)(g_V + boff);
  for (int i = t; i < 1024; i += 256) {
    ((float4*)sK)[i] = K4[i];
    ((float4*)sV)[i] = V4[i];
  }
  for (int i = t; i < DD * EE; i += 256) {
    int d = i >> 4, e = i & 15;
    sE[d * 17 + e] = emb[i];
  }
  for (int i = t; i < 1088; i += 256) sO[i] = 0.f;

  float q[16];
  {
    const float4* qp = (const float4*)(g_Q + boff + (size_t)lg * EE);
#pragma unroll
    for (int i = 0; i < 4; i++) {
      float4 v = qp[i];
      q[i * 4] = v.x; q[i * 4 + 1] = v.y; q[i * 4 + 2] = v.z; q[i * 4 + 3] = v.w;
    }
  }
  __syncthreads();

  float S[64];
  int sbase = sg * 64;
#pragma unroll
  for (int j = 0; j < 64; j++) {
    int s = sbase + j;
    int d = lg - s;
    d = (d < -MM) ? -MM : (d > MM ? MM : d);
    d += MM;
    const float4* kr = (const float4*)(sK + s * 16);
    const float* er = sE + d * 17;
    float acc = 0.f;
#pragma unroll
    for (int i = 0; i < 4; i++) {
      float4 kv = kr[i];
      float e0 = er[i * 4], e1 = er[i * 4 + 1], e2 = er[i * 4 + 2], e3 = er[i * 4 + 3];
      // q*k + q*pe + k*pe  =  q*(k+pe) + k*pe
      acc += q[i * 4 + 0] * (kv.x + e0) + kv.x * e0;
      acc += q[i * 4 + 1] * (kv.y + e1) + kv.y * e1;
      acc += q[i * 4 + 2] * (kv.z + e2) + kv.z * e2;
      acc += q[i * 4 + 3] * (kv.w + e3) + kv.w * e3;
    }
    S[j] = acc;
  }

  // softmax over full row (row is split across 4 sg-threads in different warps)
  float mx = -1e30f;
#pragma unroll
  for (int j = 0; j < 64; j++) mx = fmaxf(mx, S[j]);
  sR[l * 4 + sg] = mx;
  __syncthreads();
  float rm = fmaxf(fmaxf(sR[l * 4], sR[l * 4 + 1]), fmaxf(sR[l * 4 + 2], sR[l * 4 + 3]));
  const float scale = 0.25f;  // 1/sqrt(E)
  float sum = 0.f;
#pragma unroll
  for (int j = 0; j < 64; j++) {
    float p = __expf((S[j] - rm) * scale);
    S[j] = p;
    sum += p;
  }
  sR[256 + l * 4 + sg] = sum;  // disjoint region from the max slots
  __syncthreads();
  float rs = sR[256 + l * 4] + sR[256 + l * 4 + 1] + sR[256 + l * 4 + 2] + sR[256 + l * 4 + 3];
  float inv = 1.f / rs;

  // P @ V (partial over this thread's s-chunk)
  float o16[16];
#pragma unroll
  for (int e = 0; e < 16; e++) o16[e] = 0.f;
#pragma unroll
  for (int j = 0; j < 64; j++) {
    float p = S[j];
    const float4* vr = (const float4*)(sV + (sbase + j) * 16);
#pragma unroll
    for (int i = 0; i < 4; i++) {
      float4 vv = vr[i];
      o16[i * 4] += p * vv.x; o16[i * 4 + 1] += p * vv.y;
      o16[i * 4 + 2] += p * vv.z; o16[i * 4 + 3] += p * vv.w;
    }
  }
#pragma unroll
  for (int e = 0; e < 16; e++) o16[e] *= inv;

  // combine 4 partial rows deterministically (staged adds)
  for (int p = 0; p < 4; p++) {
    if (sg == p) {
#pragma unroll
      for (int e = 0; e < 16; e++) sO[l * 17 + e] += o16[e];
    }
    __syncthreads();
  }

  // write y[f][n][c]
  for (int i = t; i < 1024; i += 256) {
    int r = i >> 4, e = i & 15;
    g_Y[((size_t)(l0 + r) * NN + n) * CC + h * EE + e] = sO[r * 17 + e];
  }
}

// ---------------- kernel 3: gated AddNorm1 ----------------
__device__ __forceinline__ float blockSum128(float v, float* red) {
#pragma unroll
  for (int o = 16; o > 0; o >>= 1) v += __shfl_xor_sync(0xffffffffu, v, o);
  int t = threadIdx.x;
  if ((t & 31) == 0) red[t >> 5] = v;
  __syncthreads();
  float tot = red[0] + red[1] + red[2] + red[3];
  __syncthreads();
  return tot;
}

__global__ void __launch_bounds__(128) gate_ln1_kernel(
    const float* __restrict__ x, const float* __restrict__ Wb,
    const float* __restrict__ g, const float* __restrict__ b) {
  __shared__ float red[4];
  int r = blockIdx.x, c = threadIdx.x;
  size_t base = (size_t)r * CC + c;
  float xv = x[base], yv = g_Y[base];
  float z = yv * Wb[c] + xv * Wb[CC + c] + (yv - xv) * Wb[2 * CC + c];
  float zt = blockSum128(z, red);
  float gt = 1.f / (1.f + __expf(-zt));
  float u = gt * xv + (1.f - gt) * yv;
  float mu = blockSum128(u, red) * (1.f / CC);
  float du = u - mu;
  float var = blockSum128(du * du, red) * (1.f / CC);
  g_H1[base] = du * rsqrtf(var + 1e-5f) * g[c] + b[c];
}

// ---------------- kernel 4: fused FFN (GEMM-GELU-GEMM) + residual + LN2 ----------------
// grid 1600 (64 rows each), block 256 (16x16 logical). Both weight matrices resident in smem.
__global__ void __launch_bounds__(256) ffn_kernel(
    const float* __restrict__ W1, const float* __restrict__ b1,
    const float* __restrict__ W2, const float* __restrict__ b2,
    const float* __restrict__ g2, const float* __restrict__ bb2,
    float* __restrict__ out) {
  extern __shared__ float sm[];
  float* sW1 = sm;                  // 128*129
  float* sW2 = sW1 + 128 * 129;     // 128*129
  float* sA = sW2 + 128 * 129;      // 64*129  (h1 tile, later ff+h1)
  float* sT = sA + 64 * 129;        // 64*129  (gelu intermediate)
  float* sRed = sT + 64 * 129;      // 256
  float* sMu = sRed + 256;          // 64
  float* sRs = sMu + 64;            // 64

  int row0 = blockIdx.x * 64;
  int t = threadIdx.x;
  for (int i = t; i < 128 * 128; i += 256) {
    int r = i >> 7, c = i & 127;
    sW1[r * 129 + c] = W1[i];
    sW2[r * 129 + c] = W2[i];
  }
  for (int i = t; i < 64 * 128; i += 256) {
    int r = i >> 7, c = i & 127;
    sA[r * 129 + c] = g_H1[(size_t)(row0 + r) * CC + c];
  }
  __syncthreads();

  int tx = t & 15, ty = t >> 4;
  float acc[4][8];
#pragma unroll
  for (int a = 0; a < 4; a++)
#pragma unroll
    for (int b = 0; b < 8; b++) acc[a][b] = 0.f;

#pragma unroll 4
  for (int c = 0; c < CC; c++) {
    float xv[4], wv[8];
#pragma unroll
    for (int rr = 0; rr < 4; rr++) xv[rr] = sA[(ty + rr * 16) * 129 + c];
#pragma unroll
    for (int oo = 0; oo < 8; oo++) wv[oo] = sW1[(tx + oo * 16) * 129 + c];
#pragma unroll
    for (int rr = 0; rr < 4; rr++)
#pragma unroll
      for (int oo = 0; oo < 8; oo++) acc[rr][oo] += xv[rr] * wv[oo];
  }
#pragma unroll
  for (int rr = 0; rr < 4; rr++) {
    int r = ty + rr * 16;
#pragma unroll
    for (int oo = 0; oo < 8; oo++) {
      int o = tx + oo * 16;
      float v = acc[rr][oo] + b1[o];
      v = 0.5f * v * (1.f + erff(v * 0.70710678118654752f));  // exact GELU
      sT[r * 129 + o] = v;
    }
  }
  __syncthreads();

#pragma unroll
  for (int a = 0; a < 4; a++)
#pragma unroll
    for (int b = 0; b < 8; b++) acc[a][b] = 0.f;
#pragma unroll 4
  for (int c = 0; c < CC; c++) {
    float xv[4], wv[8];
#pragma unroll
    for (int rr = 0; rr < 4; rr++) xv[rr] = sT[(ty + rr * 16) * 129 + c];
#pragma unroll
    for (int oo = 0; oo < 8; oo++) wv[oo] = sW2[(tx + oo * 16) * 129 + c];
#pragma unroll
    for (int rr = 0; rr < 4; rr++)
#pragma unroll
      for (int oo = 0; oo < 8; oo++) acc[rr][oo] += xv[rr] * wv[oo];
  }
#pragma unroll
  for (int rr = 0; rr < 4; rr++) {
    int r = ty + rr * 16;
#pragma unroll
    for (int oo = 0; oo < 8; oo++) {
      int o = tx + oo * 16;
      float v = acc[rr][oo] + b2[o] + sA[r * 129 + o];  // ff + h1
      sA[r * 129 + o] = v;                              // only owner touches this slot
    }
  }
  __syncthreads();

  // LayerNorm over each of 64 rows (128 elems)
  {
    int r = t >> 2, ch = t & 3;
    float s = 0.f;
#pragma unroll 8
    for (int i = 0; i < 32; i++) s += sA[r * 129 + ch * 32 + i];
    sRed[t] = s;
  }
  __syncthreads();
  if (t < 64)
    sMu[t] = (sRed[t * 4] + sRed[t * 4 + 1] + sRed[t * 4 + 2] + sRed[t * 4 + 3]) * (1.f / CC);
  __syncthreads();
  {
    int r = t >> 2, ch = t & 3;
    float mu = sMu[r];
    float s = 0.f;
#pragma unroll 8
    for (int i = 0; i < 32; i++) {
      float d = sA[r * 129 + ch * 32 + i] - mu;
      s += d * d;
    }
    sRed[t] = s;
  }
  __syncthreads();
  if (t < 64) {
    float var = (sRed[t * 4] + sRed[t * 4 + 1] + sRed[t * 4 + 2] + sRed[t * 4 + 3]) * (1.f / CC);
    sRs[t] = rsqrtf(var + 1e-5f);
  }
  __syncthreads();
  for (int i = t; i < 64 * 128; i += 256) {
    int r = i >> 7, c = i & 127;
    float v = (sA[r * 129 + c] - sMu[r]) * sRs[r] * g2[c] + bb2[c];
    out[(size_t)(row0 + r) * CC + c] = v;
  }
}

// ---------------- launch ----------------
extern "C" void kernel_launch(void* const* d_in, const int* in_sizes, int n_in,
                              void* d_out, int out_size) {
  const float* x    = (const float*)d_in[0];
  const float* te   = (const float*)d_in[1];
  const float* Wqkv = (const float*)d_in[2];
  const float* Wtk  = (const float*)d_in[3];
  const float* Wtv  = (const float*)d_in[4];
  const float* emb  = (const float*)d_in[5];
  const float* Wb   = (const float*)d_in[6];
  const float* ln1g = (const float*)d_in[7];
  const float* ln1b = (const float*)d_in[8];
  const float* ln2g = (const float*)d_in[9];
  const float* ln2b = (const float*)d_in[10];
  const float* W1   = (const float*)d_in[11];
  const float* b1   = (const float*)d_in[12];
  const float* W2   = (const float*)d_in[13];
  const float* b2   = (const float*)d_in[14];
  float* out = (float*)d_out;

  const int smem_qkv = (128 * 129 + 64 * 128) * 4;                       // 98816
  const int smem_att = (4096 + 4096 + 4369 + 1088 + 512) * 4;            // 56644
  const int smem_ffn = (2 * 128 * 129 + 2 * 64 * 129 + 256 + 128) * 4;   // 199680

  cudaFuncSetAttribute(qkv_kernel, cudaFuncAttributeMaxDynamicSharedMemorySize, smem_qkv);
  cudaFuncSetAttribute(attn_kernel, cudaFuncAttributeMaxDynamicSharedMemorySize, smem_att);
  cudaFuncSetAttribute(ffn_kernel, cudaFuncAttributeMaxDynamicSharedMemorySize, smem_ffn);

  tree_proj_kernel<<<NN, 128>>>(te, Wtk, Wtv);
  qkv_kernel<<<dim3(FF * NN / 64, 3), 256, smem_qkv>>>(x, Wqkv);
  attn_kernel<<<dim3(FF / 64, HH, NN), 256, smem_att>>>(emb);
  gate_ln1_kernel<<<FF * NN, 128>>>(x, Wb, ln1g, ln1b);
  ffn_kernel<<<FF * NN / 64, 256, smem_ffn>>>(W1, b1, W2, b2, ln2g, ln2b, out);
}

// round 2
// speedup vs baseline: 1.2585x; 1.2585x over previous
#include <cuda_runtime.h>
#include <math.h>
#include <stdint.h>

#define FF 256   // frames (sequence length)
#define NN 400   // batch*joints (attention batch)
#define CC 128   // channels
#define HH 8     // heads
#define EE 16    // head dim
#define MM 128   // max relative pos
#define DD 257   // emb rows = 2*M+1

typedef unsigned long long u64;

// ---------- packed f32x2 helpers (Blackwell FFMA2 path; PTX-only) ----------
__device__ __forceinline__ u64 fma2_(u64 a, u64 b, u64 c) {
  u64 d; asm("fma.rn.f32x2 %0, %1, %2, %3;" : "=l"(d) : "l"(a), "l"(b), "l"(c)); return d;
}
__device__ __forceinline__ u64 add2_(u64 a, u64 b) {
  u64 d; asm("add.rn.f32x2 %0, %1, %2;" : "=l"(d) : "l"(a), "l"(b)); return d;
}
__device__ __forceinline__ u64 pack2_(float x, float y) {
  u64 d; asm("mov.b64 %0, {%1, %2};" : "=l"(d) : "f"(x), "f"(y)); return d;
}
__device__ __forceinline__ void unpack2_(u64 v, float& x, float& y) {
  asm("mov.b64 {%0, %1}, %2;" : "=f"(x), "=f"(y) : "l"(v));
}

// ---------------- scratch (device globals; no allocation allowed) ----------------
__device__ float g_tk[NN * CC];
__device__ float g_tv[NN * CC];
__device__ float g_Q[(size_t)NN * HH * FF * EE];
__device__ float g_K[(size_t)NN * HH * FF * EE];
__device__ float g_V[(size_t)NN * HH * FF * EE];
__device__ float g_Y[(size_t)FF * NN * CC];

// ---------------- kernel 0: tree_k / tree_v projections (tiny) ----------------
__global__ void __launch_bounds__(128) tree_proj_kernel(
    const float* __restrict__ te, const float* __restrict__ Wk,
    const float* __restrict__ Wv) {
  __shared__ float s[CC];
  int n = blockIdx.x, c = threadIdx.x;
  s[c] = te[n * CC + c];
  __syncthreads();
  float ak = 0.f, av = 0.f;
#pragma unroll 4
  for (int j = 0; j < CC; j++) {
    float t = s[j];
    ak += t * Wk[j * CC + c];
    av += t * Wv[j * CC + c];
  }
  g_tk[n * CC + c] = ak;
  g_tv[n * CC + c] = av;
}

// ---------------- kernel 1: QKV projection + tree add + head scatter ----------------
// grid (1600, 3). block = 256 threads (16x16 logical), 64-row x 128-col tile, K=128.
// Inner product packed along c (f32x2).
#define WP 130  // weight tile row pitch (even => 8B-aligned pairs; conflict-free)
__global__ void __launch_bounds__(256, 2) qkv_kernel(
    const float* __restrict__ x, const float* __restrict__ Wqkv) {
  extern __shared__ float sm[];
  float* sW = sm;             // 128 x 130
  float* sX = sm + 128 * WP;  // 64 x 128
  int m = blockIdx.y;
  int row0 = blockIdx.x * 64;
  int t = threadIdx.x;

  const float* Wc = Wqkv + (size_t)m * 128 * CC;
  for (int i = t; i < 128 * CC; i += 256) {
    int r = i >> 7, c = i & 127;
    sW[r * WP + c] = Wc[i];
  }
  const float4* xsrc = (const float4*)(x + (size_t)row0 * CC);
  for (int i = t; i < 64 * CC / 4; i += 256) ((float4*)sX)[i] = xsrc[i];
  __syncthreads();

  int tx = t & 15, ty = t >> 4;
  u64 acc2[4][8];
  const u64 z2 = 0ull;
#pragma unroll
  for (int a = 0; a < 4; a++)
#pragma unroll
    for (int b = 0; b < 8; b++) acc2[a][b] = z2;

#pragma unroll 4
  for (int c = 0; c < CC; c += 2) {
    u64 xv[4], wv[8];
#pragma unroll
    for (int rr = 0; rr < 4; rr++) xv[rr] = *(const u64*)(sX + (ty + rr * 16) * CC + c);
#pragma unroll
    for (int oo = 0; oo < 8; oo++) wv[oo] = *(const u64*)(sW + (tx + oo * 16) * WP + c);
#pragma unroll
    for (int rr = 0; rr < 4; rr++)
#pragma unroll
      for (int oo = 0; oo < 8; oo++) acc2[rr][oo] = fma2_(xv[rr], wv[oo], acc2[rr][oo]);
  }

  float* dst = (m == 0) ? g_Q : (m == 1) ? g_K : g_V;
  const float* tadd = (m == 1) ? g_tk : (m == 2) ? g_tv : nullptr;
#pragma unroll
  for (int rr = 0; rr < 4; rr++) {
    int r = row0 + ty + rr * 16;
    int f = r / NN, n = r - f * NN;
#pragma unroll
    for (int oo = 0; oo < 8; oo++) {
      int o = tx + oo * 16;
      float lo, hi;
      unpack2_(acc2[rr][oo], lo, hi);
      float v = lo + hi;
      if (tadd) v += tadd[n * CC + o];
      int h = o >> 4, e = o & 15;
      dst[(((size_t)(n * HH + h)) * FF + f) * EE + e] = v;
    }
  }
}

// ---------------- kernel 2: attention with relative position bias ----------------
// grid (4 l-tiles, 8 heads, 400 batch). block = 256 threads.
// thread t: l = t&63 (row in tile), sg = t>>6 (64-wide s chunk). Scores in registers.
// pe table staged as 8 float2-planes sE2[p][d] => per-lane diagonal gather is a
// contiguous conflict-free LDS.64. All dot products on the f32x2 pipe.
__global__ void __launch_bounds__(256, 2) attn_kernel(const float* __restrict__ emb) {
  extern __shared__ float sm[];
  float* sK = sm;            // 256*16 = 4096
  float* sV = sK + 4096;     // 4096
  float* sE2 = sV + 4096;    // 8 planes * 257 * 2 = 4112 (plane p: pe[d][2p],pe[d][2p+1])
  float* sO = sE2 + 4112;    // 64*17 = 1088
  float* sR = sO + 1088;     // 512

  int lt = blockIdx.x, h = blockIdx.y, n = blockIdx.z;
  int t = threadIdx.x;
  int l = t & 63, sg = t >> 6;
  int l0 = lt * 64, lg = l0 + l;
  size_t boff = ((size_t)n * HH + h) * FF * EE;

  const float4* K4 = (const float4*)(g_K + boff);
  const float4* V4 = (const float4*)(g_V + boff);
  for (int i = t; i < 1024; i += 256) {
    ((float4*)sK)[i] = K4[i];
    ((float4*)sV)[i] = V4[i];
  }
  for (int i = t; i < DD * 8; i += 256) {
    int p = i >> 8;          // 0..7  (i < 2056; plane index via /257 avoided)
    p = i / DD; int d = i - p * DD;
    *(float2*)(sE2 + (p * DD + d) * 2) = *(const float2*)(emb + d * EE + 2 * p);
  }
  for (int i = t; i < 1088; i += 256) sO[i] = 0.f;

  u64 q2[8];
  {
    const float* qp = g_Q + boff + (size_t)lg * EE;
#pragma unroll
    for (int p = 0; p < 8; p++) q2[p] = *(const u64*)(qp + 2 * p);
  }
  __syncthreads();

  float S[64];
  int sbase = sg * 64;
#pragma unroll
  for (int j = 0; j < 64; j++) {
    int s = sbase + j;
    int d = lg - s;
    d = (d < -MM) ? -MM : (d > MM ? MM : d);
    d += MM;
    const float* kr = sK + s * 16;
    const float* er = sE2 + d * 2;
    u64 acc = 0ull;
#pragma unroll
    for (int p = 0; p < 8; p++) {
      u64 k2 = *(const u64*)(kr + 2 * p);            // broadcast across warp
      u64 e2 = *(const u64*)(er + p * (DD * 2));     // contiguous per-lane
      // q*k + q*pe + k*pe  =  q*(k+pe) + k*pe
      acc = fma2_(q2[p], add2_(k2, e2), acc);
      acc = fma2_(k2, e2, acc);
    }
    float lo, hi;
    unpack2_(acc, lo, hi);
    S[j] = lo + hi;
  }

  // softmax over full row (row split across 4 sg-threads)
  float mx = -1e30f;
#pragma unroll
  for (int j = 0; j < 64; j++) mx = fmaxf(mx, S[j]);
  sR[l * 4 + sg] = mx;
  __syncthreads();
  float rm = fmaxf(fmaxf(sR[l * 4], sR[l * 4 + 1]), fmaxf(sR[l * 4 + 2], sR[l * 4 + 3]));
  const float scale = 0.25f;  // 1/sqrt(E)
  float sum = 0.f;
#pragma unroll
  for (int j = 0; j < 64; j++) {
    float p = __expf((S[j] - rm) * scale);
    S[j] = p;
    sum += p;
  }
  sR[256 + l * 4 + sg] = sum;
  __syncthreads();
  float rs = sR[256 + l * 4] + sR[256 + l * 4 + 1] + sR[256 + l * 4 + 2] + sR[256 + l * 4 + 3];
  float inv = 1.f / rs;

  // P @ V (partial over this thread's s-chunk), packed over e
  u64 o2[8];
#pragma unroll
  for (int p = 0; p < 8; p++) o2[p] = 0ull;
#pragma unroll
  for (int j = 0; j < 64; j++) {
    u64 p2 = pack2_(S[j], S[j]);
    const float* vr = sV + (sbase + j) * 16;
#pragma unroll
    for (int p = 0; p < 8; p++) o2[p] = fma2_(p2, *(const u64*)(vr + 2 * p), o2[p]);
  }
  float o16[16];
#pragma unroll
  for (int p = 0; p < 8; p++) {
    float lo, hi;
    unpack2_(o2[p], lo, hi);
    o16[2 * p] = lo * inv;
    o16[2 * p + 1] = hi * inv;
  }

  // combine 4 partial rows deterministically (staged adds)
  for (int p = 0; p < 4; p++) {
    if (sg == p) {
#pragma unroll
      for (int e = 0; e < 16; e++) sO[l * 17 + e] += o16[e];
    }
    __syncthreads();
  }

  // write y[f][n][c]
  for (int i = t; i < 1024; i += 256) {
    int r = i >> 4, e = i & 15;
    g_Y[((size_t)(l0 + r) * NN + n) * CC + h * EE + e] = sO[r * 17 + e];
  }
}

// ---------------- kernel 3: fused gate+AddNorm1 + FFN + residual + LN2 ----------------
// grid 1600 (64 rows each), block 256. Both weight matrices resident in smem.
__global__ void __launch_bounds__(256) ffn_kernel(
    const float* __restrict__ x, const float* __restrict__ Wbeta,
    const float* __restrict__ g1, const float* __restrict__ bb1,
    const float* __restrict__ W1, const float* __restrict__ b1,
    const float* __restrict__ W2, const float* __restrict__ b2,
    const float* __restrict__ g2, const float* __restrict__ bb2,
    float* __restrict__ out) {
  extern __shared__ float sm[];
  float* sW1 = sm;                 // 128*130
  float* sW2 = sW1 + 128 * WP;     // 128*130
  float* sA = sW2 + 128 * WP;      // 64*130  (x -> u -> h1 -> ff+h1)
  float* sT = sA + 64 * WP;        // 64*130  (y -> gelu intermediate)
  float* sWb = sT + 64 * WP;       // 384
  float* sRed = sWb + 384;         // 256
  float* sMu = sRed + 256;         // 64 (gate, then mean)
  float* sRs = sMu + 64;           // 64

  int row0 = blockIdx.x * 64;
  int t = threadIdx.x;
  for (int i = t; i < 128 * 128; i += 256) {
    int r = i >> 7, c = i & 127;
    sW1[r * WP + c] = W1[i];
    sW2[r * WP + c] = W2[i];
  }
  for (int i = t; i < 64 * 128; i += 256) {
    int r = i >> 7, c = i & 127;
    size_t gi = (size_t)(row0 + r) * CC + c;
    sA[r * WP + c] = x[gi];
    sT[r * WP + c] = g_Y[gi];
  }
  for (int i = t; i < 384; i += 256) sWb[i] = Wbeta[i];
  __syncthreads();

  // ---- gate: z row-sum, sigmoid ----
  {
    int r = t >> 2, ch = t & 3;
    float ssum = 0.f;
#pragma unroll 8
    for (int i = 0; i < 32; i++) {
      int c = ch * 32 + i;
      float xv = sA[r * WP + c], yv = sT[r * WP + c];
      ssum += yv * sWb[c] + xv * sWb[CC + c] + (yv - xv) * sWb[2 * CC + c];
    }
    sRed[t] = ssum;
  }
  __syncthreads();
  if (t < 64) {
    float z = sRed[t * 4] + sRed[t * 4 + 1] + sRed[t * 4 + 2] + sRed[t * 4 + 3];
    sMu[t] = 1.f / (1.f + __expf(-z));  // gate per row
  }
  __syncthreads();
  // ---- u = g*x + (1-g)*y (overwrite sA) ----
  for (int i = t; i < 64 * 128; i += 256) {
    int r = i >> 7, c = i & 127;
    float gt = sMu[r];
    sA[r * WP + c] = gt * sA[r * WP + c] + (1.f - gt) * sT[r * WP + c];
  }
  __syncthreads();
  // ---- LayerNorm1 ----
  {
    int r = t >> 2, ch = t & 3;
    float s = 0.f;
#pragma unroll 8
    for (int i = 0; i < 32; i++) s += sA[r * WP + ch * 32 + i];
    sRed[t] = s;
  }
  __syncthreads();
  if (t < 64)
    sMu[t] = (sRed[t * 4] + sRed[t * 4 + 1] + sRed[t * 4 + 2] + sRed[t * 4 + 3]) * (1.f / CC);
  __syncthreads();
  {
    int r = t >> 2, ch = t & 3;
    float mu = sMu[r], s = 0.f;
#pragma unroll 8
    for (int i = 0; i < 32; i++) {
      float d = sA[r * WP + ch * 32 + i] - mu;
      s += d * d;
    }
    sRed[t] = s;
  }
  __syncthreads();
  if (t < 64) {
    float var = (sRed[t * 4] + sRed[t * 4 + 1] + sRed[t * 4 + 2] + sRed[t * 4 + 3]) * (1.f / CC);
    sRs[t] = rsqrtf(var + 1e-5f);
  }
  __syncthreads();
  for (int i = t; i < 64 * 128; i += 256) {
    int r = i >> 7, c = i & 127;
    sA[r * WP + c] = (sA[r * WP + c] - sMu[r]) * sRs[r] * g1[c] + bb1[c];
  }
  __syncthreads();

  // ---- GEMM1 + GELU (packed f32x2 along c) ----
  int tx = t & 15, ty = t >> 4;
  u64 acc2[4][8];
#pragma unroll
  for (int a = 0; a < 4; a++)
#pragma unroll
    for (int b = 0; b < 8; b++) acc2[a][b] = 0ull;
#pragma unroll 4
  for (int c = 0; c < CC; c += 2) {
    u64 xv[4], wv[8];
#pragma unroll
    for (int rr = 0; rr < 4; rr++) xv[rr] = *(const u64*)(sA + (ty + rr * 16) * WP + c);
#pragma unroll
    for (int oo = 0; oo < 8; oo++) wv[oo] = *(const u64*)(sW1 + (tx + oo * 16) * WP + c);
#pragma unroll
    for (int rr = 0; rr < 4; rr++)
#pragma unroll
      for (int oo = 0; oo < 8; oo++) acc2[rr][oo] = fma2_(xv[rr], wv[oo], acc2[rr][oo]);
  }
  __syncthreads();  // sT (y) dead; about to overwrite
#pragma unroll
  for (int rr = 0; rr < 4; rr++) {
    int r = ty + rr * 16;
#pragma unroll
    for (int oo = 0; oo < 8; oo++) {
      int o = tx + oo * 16;
      float lo, hi;
      unpack2_(acc2[rr][oo], lo, hi);
      float v = lo + hi + b1[o];
      v = 0.5f * v * (1.f + erff(v * 0.70710678118654752f));  // exact GELU
      sT[r * WP + o] = v;
    }
  }
  __syncthreads();

  // ---- GEMM2 + residual ----
#pragma unroll
  for (int a = 0; a < 4; a++)
#pragma unroll
    for (int b = 0; b < 8; b++) acc2[a][b] = 0ull;
#pragma unroll 4
  for (int c = 0; c < CC; c += 2) {
    u64 xv[4], wv[8];
#pragma unroll
    for (int rr = 0; rr < 4; rr++) xv[rr] = *(const u64*)(sT + (ty + rr * 16) * WP + c);
#pragma unroll
    for (int oo = 0; oo < 8; oo++) wv[oo] = *(const u64*)(sW2 + (tx + oo * 16) * WP + c);
#pragma unroll
    for (int rr = 0; rr < 4; rr++)
#pragma unroll
      for (int oo = 0; oo < 8; oo++) acc2[rr][oo] = fma2_(xv[rr], wv[oo], acc2[rr][oo]);
  }
#pragma unroll
  for (int rr = 0; rr < 4; rr++) {
    int r = ty + rr * 16;
#pragma unroll
    for (int oo = 0; oo < 8; oo++) {
      int o = tx + oo * 16;
      float lo, hi;
      unpack2_(acc2[rr][oo], lo, hi);
      sA[r * WP + o] = lo + hi + b2[o] + sA[r * WP + o];  // ff + h1 (owner slot)
    }
  }
  __syncthreads();

  // ---- LayerNorm2 + store ----
  {
    int r = t >> 2, ch = t & 3;
    float s = 0.f;
#pragma unroll 8
    for (int i = 0; i < 32; i++) s += sA[r * WP + ch * 32 + i];
    sRed[t] = s;
  }
  __syncthreads();
  if (t < 64)
    sMu[t] = (sRed[t * 4] + sRed[t * 4 + 1] + sRed[t * 4 + 2] + sRed[t * 4 + 3]) * (1.f / CC);
  __syncthreads();
  {
    int r = t >> 2, ch = t & 3;
    float mu = sMu[r], s = 0.f;
#pragma unroll 8
    for (int i = 0; i < 32; i++) {
      float d = sA[r * WP + ch * 32 + i] - mu;
      s += d * d;
    }
    sRed[t] = s;
  }
  __syncthreads();
  if (t < 64) {
    float var = (sRed[t * 4] + sRed[t * 4 + 1] + sRed[t * 4 + 2] + sRed[t * 4 + 3]) * (1.f / CC);
    sRs[t] = rsqrtf(var + 1e-5f);
  }
  __syncthreads();
  for (int i = t; i < 64 * 128; i += 256) {
    int r = i >> 7, c = i & 127;
    float v = (sA[r * WP + c] - sMu[r]) * sRs[r] * g2[c] + bb2[c];
    out[(size_t)(row0 + r) * CC + c] = v;
  }
}

// ---------------- launch ----------------
extern "C" void kernel_launch(void* const* d_in, const int* in_sizes, int n_in,
                              void* d_out, int out_size) {
  const float* x    = (const float*)d_in[0];
  const float* te   = (const float*)d_in[1];
  const float* Wqkv = (const float*)d_in[2];
  const float* Wtk  = (const float*)d_in[3];
  const float* Wtv  = (const float*)d_in[4];
  const float* emb  = (const float*)d_in[5];
  const float* Wb   = (const float*)d_in[6];
  const float* ln1g = (const float*)d_in[7];
  const float* ln1b = (const float*)d_in[8];
  const float* ln2g = (const float*)d_in[9];
  const float* ln2b = (const float*)d_in[10];
  const float* W1   = (const float*)d_in[11];
  const float* b1   = (const float*)d_in[12];
  const float* W2   = (const float*)d_in[13];
  const float* b2   = (const float*)d_in[14];
  float* out = (float*)d_out;

  const int smem_qkv = (128 * WP + 64 * CC) * 4;                              // 99328
  const int smem_att = (4096 + 4096 + 4112 + 1088 + 512) * 4;                 // 55616
  const int smem_ffn = (2 * 128 * WP + 2 * 64 * WP + 384 + 256 + 64 + 64) * 4;// 202752

  cudaFuncSetAttribute(qkv_kernel, cudaFuncAttributeMaxDynamicSharedMemorySize, smem_qkv);
  cudaFuncSetAttribute(attn_kernel, cudaFuncAttributeMaxDynamicSharedMemorySize, smem_att);
  cudaFuncSetAttribute(ffn_kernel, cudaFuncAttributeMaxDynamicSharedMemorySize, smem_ffn);

  tree_proj_kernel<<<NN, 128>>>(te, Wtk, Wtv);
  qkv_kernel<<<dim3(FF * NN / 64, 3), 256, smem_qkv>>>(x, Wqkv);
  attn_kernel<<<dim3(FF / 64, HH, NN), 256, smem_att>>>(emb);
  ffn_kernel<<<FF * NN / 64, 256, smem_ffn>>>(x, Wb, ln1g, ln1b, W1, b1, W2, b2,
                                              ln2g, ln2b, out);
}